// round 2
// baseline (speedup 1.0000x reference)
#include <cuda_runtime.h>
#include <cstdint>

#define NC 32
#define NSTEPS 32
#define DDIM 30
#define TPB 256
#define PPT 8   // consecutive points per thread

// Lane-replicated table: tab[cell*32 + lane] (float2). Lane l always reads
// banks (2l, 2l+1) -> conflict-free regardless of data-dependent cell values.
__global__ __launch_bounds__(TPB) void cpab_kernel(
    const float4* __restrict__ points4,
    const float* __restrict__ theta,
    const float* __restrict__ basis,
    float4* __restrict__ out4,
    int n_points)
{
    __shared__ float2 tab[NC * 32];
    __shared__ float2 coef[NC];

    const int t   = blockIdx.y;
    const int tid = threadIdx.x;

    // ---- build per-theta table (32 cells), scaled to y = 32*x coordinates ----
    if (tid < NC) {
        const int c = tid;
        const float* __restrict__ th = theta + t * DDIM;
        const float* __restrict__ ba = basis + (2 * c) * DDIM;
        const float* __restrict__ bb = basis + (2 * c + 1) * DDIM;
        float a = 0.0f, b = 0.0f;
        #pragma unroll
        for (int j = 0; j < DDIM; j++) {
            a = fmaf(ba[j], th[j], a);
            b = fmaf(bb[j], th[j], b);
        }
        const float dT = 1.0f / (float)NSTEPS;
        float ad = dT * a;
        float bd = dT * b;
        float phi = (fabsf(ad) < 1e-6f) ? (1.0f + 0.5f * ad) : (expm1f(ad) / ad);
        // y' = e^a * y + 32*b*phi   (exactly 32x the reference recurrence)
        coef[c] = make_float2(expf(ad), 32.0f * bd * phi);
    }
    __syncthreads();

    #pragma unroll
    for (int i = tid; i < NC * 32; i += TPB)
        tab[i] = coef[i >> 5];
    __syncthreads();

    const int lane = tid & 31;
    const uint32_t sbase =
        (uint32_t)__cvta_generic_to_shared(tab) + (uint32_t)(lane * 8);

    // ---- load 8 consecutive points (2x float4) ----
    const int f4 = blockIdx.x * (TPB * 2) + tid * 2;
    float4 p0 = points4[f4];
    float4 p1 = points4[f4 + 1];

    float y[PPT];
    y[0] = 32.0f * p0.x;  y[1] = 32.0f * p0.y;
    y[2] = 32.0f * p0.z;  y[3] = 32.0f * p0.w;
    y[4] = 32.0f * p1.x;  y[5] = 32.0f * p1.y;
    y[6] = 32.0f * p1.z;  y[7] = 32.0f * p1.w;

    #pragma unroll 4
    for (int s = 0; s < NSTEPS; s++) {
        #pragma unroll
        for (int k = 0; k < PPT; k++) {
            // cell = floor(clamp(y, 0, 31)); RZ magic-add puts floor(v) in
            // the low mantissa bits; (bits<<8) == cell*256 since
            // 0x4B000000<<8 wraps to 0 mod 2^32.
            float v = fminf(fmaxf(y[k], 0.0f), 31.0f);
            float u = __fadd_rz(v, 8388608.0f);       // 2^23
            uint32_t addr = sbase + (((uint32_t)__float_as_int(u)) << 8);
            float ea, bp;
            asm volatile("ld.shared.v2.f32 {%0, %1}, [%2];"
                         : "=f"(ea), "=f"(bp) : "r"(addr));
            y[k] = fmaf(ea, y[k], bp);
        }
    }

    // ---- write back x = y/32 (exact) ----
    const float inv = 1.0f / 32.0f;
    float4 o0, o1;
    o0.x = y[0] * inv;  o0.y = y[1] * inv;
    o0.z = y[2] * inv;  o0.w = y[3] * inv;
    o1.x = y[4] * inv;  o1.y = y[5] * inv;
    o1.z = y[6] * inv;  o1.w = y[7] * inv;

    float4* __restrict__ o = out4 + ((size_t)t * n_points) / 4;
    o[f4]     = o0;
    o[f4 + 1] = o1;
}

extern "C" void kernel_launch(void* const* d_in, const int* in_sizes, int n_in,
                              void* d_out, int out_size) {
    const float* points = (const float*)d_in[0];   // [1, n_points]
    const float* theta  = (const float*)d_in[1];   // [n_theta, 30]
    const float* basis  = (const float*)d_in[2];   // [64, 30]
    float* out = (float*)d_out;                    // [n_theta, 1, n_points]

    const int n_points = in_sizes[0];
    const int n_theta  = in_sizes[1] / DDIM;

    dim3 grid(n_points / (TPB * PPT), n_theta);
    cpab_kernel<<<grid, TPB>>>((const float4*)points, theta, basis,
                               (float4*)out, n_points);
}

// round 3
// speedup vs baseline: 1.3957x; 1.3957x over previous
#include <cuda_runtime.h>
#include <cstdint>

#define NC 32
#define NSTEPS 32
#define DDIM 30
#define TPB 256
#define PPT 4   // 4 consecutive points per thread (one float4)

// Lane-replicated table: tab[cell*32 + lane] (float2). Lane l always reads
// banks (2l, 2l+1) -> conflict-free regardless of data-dependent cell values.
__global__ __launch_bounds__(TPB) void cpab_kernel(
    const float4* __restrict__ points4,
    const float* __restrict__ theta,
    const float* __restrict__ basis,
    float4* __restrict__ out4,
    int n_points)
{
    __shared__ float2 tab[NC * 32];
    __shared__ float2 coef[NC];

    const int t   = blockIdx.y;
    const int tid = threadIdx.x;

    // ---- build per-theta table (32 cells), scaled to y = 32*x coordinates ----
    if (tid < NC) {
        const int c = tid;
        const float* __restrict__ th = theta + t * DDIM;
        const float* __restrict__ ba = basis + (2 * c) * DDIM;
        const float* __restrict__ bb = basis + (2 * c + 1) * DDIM;
        float a = 0.0f, b = 0.0f;
        #pragma unroll
        for (int j = 0; j < DDIM; j++) {
            a = fmaf(ba[j], th[j], a);
            b = fmaf(bb[j], th[j], b);
        }
        const float dT = 1.0f / (float)NSTEPS;
        float ad = dT * a;
        float bd = dT * b;
        float phi = (fabsf(ad) < 1e-6f) ? (1.0f + 0.5f * ad) : (expm1f(ad) / ad);
        // y' = e^a * y + 32*b*phi   (exactly 32x the reference recurrence)
        coef[c] = make_float2(expf(ad), 32.0f * bd * phi);
    }
    __syncthreads();

    #pragma unroll
    for (int i = tid; i < NC * 32; i += TPB)
        tab[i] = coef[i >> 5];
    __syncthreads();

    const int lane = tid & 31;
    const uint32_t sbase =
        (uint32_t)__cvta_generic_to_shared(tab) + (uint32_t)(lane * 8);

    // ---- load 4 consecutive points ----
    const int f4 = blockIdx.x * TPB + tid;
    float4 p = points4[f4];

    float y[PPT];
    y[0] = 32.0f * p.x;  y[1] = 32.0f * p.y;
    y[2] = 32.0f * p.z;  y[3] = 32.0f * p.w;

    #pragma unroll 8
    for (int s = 0; s < NSTEPS; s++) {
        #pragma unroll
        for (int k = 0; k < PPT; k++) {
            // cell = floor(clamp(y, 0, 31)); RZ magic-add puts floor(v) in the
            // low mantissa; (bits<<8) == cell*256 since 0x4B000000<<8 wraps
            // to 0 mod 2^32 -> single LEA.SHL folds shift + base add.
            float v = fminf(fmaxf(y[k], 0.0f), 31.0f);
            float u = __fadd_rz(v, 8388608.0f);       // 2^23
            uint32_t addr = sbase + (((uint32_t)__float_as_int(u)) << 8);
            float ea, bp;
            asm volatile("ld.shared.v2.f32 {%0, %1}, [%2];"
                         : "=f"(ea), "=f"(bp) : "r"(addr));
            y[k] = fmaf(ea, y[k], bp);
        }
    }

    // ---- write back x = y/32 (exact) ----
    const float inv = 1.0f / 32.0f;
    float4 o;
    o.x = y[0] * inv;  o.y = y[1] * inv;
    o.z = y[2] * inv;  o.w = y[3] * inv;

    float4* __restrict__ op = out4 + ((size_t)t * n_points) / 4;
    op[f4] = o;
}

extern "C" void kernel_launch(void* const* d_in, const int* in_sizes, int n_in,
                              void* d_out, int out_size) {
    const float* points = (const float*)d_in[0];   // [1, n_points]
    const float* theta  = (const float*)d_in[1];   // [n_theta, 30]
    const float* basis  = (const float*)d_in[2];   // [64, 30]
    float* out = (float*)d_out;                    // [n_theta, 1, n_points]

    const int n_points = in_sizes[0];
    const int n_theta  = in_sizes[1] / DDIM;

    dim3 grid(n_points / (TPB * PPT), n_theta);
    cpab_kernel<<<grid, TPB>>>((const float4*)points, theta, basis,
                               (float4*)out, n_points);
}

// round 4
// speedup vs baseline: 1.5376x; 1.1017x over previous
#include <cuda_runtime.h>
#include <cstdint>

#define NC 32
#define NSTEPS 32
#define DDIM 30
#define TPB 256
#define PPT 8   // 8 consecutive points per thread: 4 LDS chains + 4 SHFL chains

__global__ __launch_bounds__(TPB, 7) void cpab_kernel(
    const float4* __restrict__ points4,
    const float* __restrict__ theta,
    const float* __restrict__ basis,
    float4* __restrict__ out4,
    int n_points)
{
    __shared__ float2 tab[NC * 32];   // lane-replicated: tab[cell*32 + lane]
    __shared__ float2 coef[NC];

    const int t   = blockIdx.y;
    const int tid = threadIdx.x;

    // ---- build per-theta table, scaled to y = 32*x coordinates ----
    if (tid < NC) {
        const int c = tid;
        const float* __restrict__ th = theta + t * DDIM;
        const float* __restrict__ ba = basis + (2 * c) * DDIM;
        const float* __restrict__ bb = basis + (2 * c + 1) * DDIM;
        float a = 0.0f, b = 0.0f;
        #pragma unroll
        for (int j = 0; j < DDIM; j++) {
            a = fmaf(ba[j], th[j], a);
            b = fmaf(bb[j], th[j], b);
        }
        const float dT = 1.0f / (float)NSTEPS;
        float ad = dT * a;
        float bd = dT * b;
        float phi = (fabsf(ad) < 1e-6f) ? (1.0f + 0.5f * ad) : (expm1f(ad) / ad);
        coef[c] = make_float2(expf(ad), 32.0f * bd * phi);
    }
    __syncthreads();

    #pragma unroll
    for (int i = tid; i < NC * 32; i += TPB)
        tab[i] = coef[i >> 5];
    __syncthreads();

    const int lane = tid & 31;
    // register-resident copy of the table for the SHFL path: lane l owns cell l
    const float ea_r = coef[lane].x;
    const float bp_r = coef[lane].y;

    const uint32_t sbase =
        (uint32_t)__cvta_generic_to_shared(tab) + (uint32_t)(lane * 8);

    // ---- load 8 consecutive points (2x float4) ----
    const int f4 = blockIdx.x * (TPB * 2) + tid * 2;
    float4 p0 = points4[f4];
    float4 p1 = points4[f4 + 1];

    float y[PPT];
    y[0] = 32.0f * p0.x;  y[1] = 32.0f * p0.y;
    y[2] = 32.0f * p0.z;  y[3] = 32.0f * p0.w;
    y[4] = 32.0f * p1.x;  y[5] = 32.0f * p1.y;
    y[6] = 32.0f * p1.z;  y[7] = 32.0f * p1.w;

    #pragma unroll 2
    for (int s = 0; s < NSTEPS; s++) {
        // chains 0..3: LDS path (tab[cell*32 + lane], conflict-free by layout)
        #pragma unroll
        for (int k = 0; k < 4; k++) {
            float v = fminf(fmaxf(y[k], 0.0f), 31.0f);
            float u = __fadd_rz(v, 8388608.0f);       // 2^23: low bits = cell
            uint32_t addr = sbase + (((uint32_t)__float_as_int(u)) << 8);
            float ea, bp;
            asm("ld.shared.v2.f32 {%0, %1}, [%2];"
                : "=f"(ea), "=f"(bp) : "r"(addr));
            y[k] = fmaf(ea, y[k], bp);
        }
        // chains 4..7: SHFL path (warp-register table, index = low 5 bits)
        #pragma unroll
        for (int k = 4; k < PPT; k++) {
            float v = fminf(fmaxf(y[k], 0.0f), 31.0f);
            float u = __fadd_rz(v, 8388608.0f);
            int idx = __float_as_int(u);              // shfl masks to low 5 bits
            float ea = __shfl_sync(0xffffffffu, ea_r, idx);
            float bp = __shfl_sync(0xffffffffu, bp_r, idx);
            y[k] = fmaf(ea, y[k], bp);
        }
    }

    // ---- write back x = y/32 (exact) ----
    const float inv = 1.0f / 32.0f;
    float4 o0, o1;
    o0.x = y[0] * inv;  o0.y = y[1] * inv;
    o0.z = y[2] * inv;  o0.w = y[3] * inv;
    o1.x = y[4] * inv;  o1.y = y[5] * inv;
    o1.z = y[6] * inv;  o1.w = y[7] * inv;

    float4* __restrict__ op = out4 + ((size_t)t * n_points) / 4;
    op[f4]     = o0;
    op[f4 + 1] = o1;
}

extern "C" void kernel_launch(void* const* d_in, const int* in_sizes, int n_in,
                              void* d_out, int out_size) {
    const float* points = (const float*)d_in[0];   // [1, n_points]
    const float* theta  = (const float*)d_in[1];   // [n_theta, 30]
    const float* basis  = (const float*)d_in[2];   // [64, 30]
    float* out = (float*)d_out;                    // [n_theta, 1, n_points]

    const int n_points = in_sizes[0];
    const int n_theta  = in_sizes[1] / DDIM;

    dim3 grid(n_points / (TPB * PPT), n_theta);
    cpab_kernel<<<grid, TPB>>>((const float4*)points, theta, basis,
                               (float4*)out, n_points);
}